// round 4
// baseline (speedup 1.0000x reference)
#include <cuda_runtime.h>
#include <math.h>

// Problem constants
#define SEQ   4096
#define NH    16
#define HD    64
#define DIM   1024
#define NQKV  3072
#define WIN_HALF 128
#define NGLOB 64

// Device-global scratch (allocation-free rule: use __device__ globals)
__device__ float g_Q[NH * SEQ * HD];     // [H][S][D]
__device__ float g_K[NH * SEQ * HD];
__device__ float g_V[NH * SEQ * HD];
__device__ float g_attn[SEQ * DIM];      // [S][H*D]

// ---------------------------------------------------------------------------
// Tiled SGEMM: C = A[M,K] @ B[K,N].  BM=BN=64, BK=16, 256 threads, 4x4 micro.
// Two variants: QKV (scatter epilogue into g_Q/g_K/g_V) and plain (d_out).
// ---------------------------------------------------------------------------

__global__ void qkv_gemm_kernel(const float* __restrict__ A,   // x [4096,1024]
                                const float* __restrict__ B)   // w_qkv [1024,3072]
{
    __shared__ float As[16][68];   // [k][m], padded
    __shared__ float Bs[16][68];   // [k][n], padded

    const int tid = threadIdx.x;
    const int ty = tid >> 4;          // 0..15
    const int tx = tid & 15;          // 0..15
    const int m0 = blockIdx.y * 64;
    const int n0 = blockIdx.x * 64;

    const int arow  = tid >> 2;           // 0..63
    const int acol4 = (tid & 3) * 4;      // 0,4,8,12
    const int brow  = tid >> 4;           // 0..15
    const int bcol4 = (tid & 15) * 4;     // 0..60

    float acc[4][4];
#pragma unroll
    for (int i = 0; i < 4; i++)
#pragma unroll
        for (int j = 0; j < 4; j++) acc[i][j] = 0.0f;

    for (int k0 = 0; k0 < DIM; k0 += 16) {
        float4 av = *reinterpret_cast<const float4*>(A + (size_t)(m0 + arow) * DIM + k0 + acol4);
        As[acol4 + 0][arow] = av.x;
        As[acol4 + 1][arow] = av.y;
        As[acol4 + 2][arow] = av.z;
        As[acol4 + 3][arow] = av.w;

        float4 bv = *reinterpret_cast<const float4*>(B + (size_t)(k0 + brow) * NQKV + n0 + bcol4);
        Bs[brow][bcol4 + 0] = bv.x;
        Bs[brow][bcol4 + 1] = bv.y;
        Bs[brow][bcol4 + 2] = bv.z;
        Bs[brow][bcol4 + 3] = bv.w;

        __syncthreads();

#pragma unroll
        for (int k = 0; k < 16; k++) {
            float a[4], b[4];
#pragma unroll
            for (int i = 0; i < 4; i++) a[i] = As[k][ty * 4 + i];
#pragma unroll
            for (int j = 0; j < 4; j++) b[j] = Bs[k][tx * 4 + j];
#pragma unroll
            for (int i = 0; i < 4; i++)
#pragma unroll
                for (int j = 0; j < 4; j++) acc[i][j] = fmaf(a[i], b[j], acc[i][j]);
        }
        __syncthreads();
    }

    // Scatter epilogue: each block's 64 output columns are one (t, h) slice.
    const int t = n0 >> 10;                 // 0=Q, 1=K, 2=V
    const int h = (n0 & 1023) >> 6;         // head
    float* dst = (t == 0) ? g_Q : (t == 1) ? g_K : g_V;
    float* base = dst + (size_t)h * SEQ * HD;

#pragma unroll
    for (int i = 0; i < 4; i++) {
        const int s = m0 + ty * 4 + i;
#pragma unroll
        for (int j = 0; j < 4; j++) {
            const int d = tx * 4 + j;
            base[(size_t)s * HD + d] = acc[i][j];
        }
    }
}

__global__ void out_gemm_kernel(const float* __restrict__ B,   // w_out [1024,1024]
                                float* __restrict__ C)         // out [4096,1024]
{
    __shared__ float As[16][68];
    __shared__ float Bs[16][68];

    const int tid = threadIdx.x;
    const int ty = tid >> 4;
    const int tx = tid & 15;
    const int m0 = blockIdx.y * 64;
    const int n0 = blockIdx.x * 64;

    const int arow  = tid >> 2;
    const int acol4 = (tid & 3) * 4;
    const int brow  = tid >> 4;
    const int bcol4 = (tid & 15) * 4;

    const float* A = g_attn;   // [4096,1024]

    float acc[4][4];
#pragma unroll
    for (int i = 0; i < 4; i++)
#pragma unroll
        for (int j = 0; j < 4; j++) acc[i][j] = 0.0f;

    for (int k0 = 0; k0 < DIM; k0 += 16) {
        float4 av = *reinterpret_cast<const float4*>(A + (size_t)(m0 + arow) * DIM + k0 + acol4);
        As[acol4 + 0][arow] = av.x;
        As[acol4 + 1][arow] = av.y;
        As[acol4 + 2][arow] = av.z;
        As[acol4 + 3][arow] = av.w;

        float4 bv = *reinterpret_cast<const float4*>(B + (size_t)(k0 + brow) * DIM + n0 + bcol4);
        Bs[brow][bcol4 + 0] = bv.x;
        Bs[brow][bcol4 + 1] = bv.y;
        Bs[brow][bcol4 + 2] = bv.z;
        Bs[brow][bcol4 + 3] = bv.w;

        __syncthreads();

#pragma unroll
        for (int k = 0; k < 16; k++) {
            float a[4], b[4];
#pragma unroll
            for (int i = 0; i < 4; i++) a[i] = As[k][ty * 4 + i];
#pragma unroll
            for (int j = 0; j < 4; j++) b[j] = Bs[k][tx * 4 + j];
#pragma unroll
            for (int i = 0; i < 4; i++)
#pragma unroll
                for (int j = 0; j < 4; j++) acc[i][j] = fmaf(a[i], b[j], acc[i][j]);
        }
        __syncthreads();
    }

#pragma unroll
    for (int i = 0; i < 4; i++) {
        const int s = m0 + ty * 4 + i;
#pragma unroll
        for (int j = 0; j < 4; j++) {
            C[(size_t)s * DIM + n0 + tx * 4 + j] = acc[i][j];
        }
    }
}

// ---------------------------------------------------------------------------
// Attention: one block per (64-query tile, head). Flash-style online softmax
// over <=4 key tiles of 64 (global tile [0,64) first, then the local causal
// band tiles; band tiles that would alias the global tile are skipped).
// 256 threads, each owns a 4x4 micro-tile of the 64x64 score / output tiles.
// ---------------------------------------------------------------------------

#define SP 65   // padded row stride for 64-wide shared tiles

__global__ void attn_kernel()
{
    extern __shared__ float sm[];
    float* Qs = sm;                 // 64 x SP
    float* Ks = Qs + 64 * SP;       // 64 x SP
    float* Vs = Ks + 64 * SP;       // 64 x SP
    float* Ss = Vs + 64 * SP;       // 64 x SP

    const int h  = blockIdx.y;
    const int qt = blockIdx.x;
    const int qbase = qt * 64;

    const int tid = threadIdx.x;
    const int ty = tid >> 4;   // row group
    const int tx = tid & 15;   // col group

    const float* Qh = g_Q + (size_t)h * SEQ * HD;
    const float* Kh = g_K + (size_t)h * SEQ * HD;
    const float* Vh = g_V + (size_t)h * SEQ * HD;

    // Load Q tile [64 x 64]
#pragma unroll
    for (int e = 0; e < 16; e++) {
        const int idx = tid + e * 256;
        const int r = idx >> 6, c = idx & 63;
        Qs[r * SP + c] = Qh[(size_t)(qbase + r) * HD + c];
    }

    float m_r[4], l_r[4], acc[4][4];
#pragma unroll
    for (int i = 0; i < 4; i++) {
        m_r[i] = -1e30f;
        l_r[i] = 0.0f;
#pragma unroll
        for (int j = 0; j < 4; j++) acc[i][j] = 0.0f;
    }

    // Key-tile starts: global tile first (guarantees finite row max on tile 0),
    // then band tiles qbase-128, qbase-64, qbase when strictly > 0.
    int starts[4];
    int ns = 0;
    starts[ns++] = 0;
    if (qbase - 128 > 0) starts[ns++] = qbase - 128;
    if (qbase - 64  > 0) starts[ns++] = qbase - 64;
    if (qbase       > 0) starts[ns++] = qbase;

    const float scale = 0.125f;  // 1/sqrt(64)

    for (int it = 0; it < ns; it++) {
        const int kst = starts[it];

        __syncthreads();  // previous tile's Vs/Ss readers done

        // Load K,V tiles [64 x 64]
#pragma unroll
        for (int e = 0; e < 16; e++) {
            const int idx = tid + e * 256;
            const int r = idx >> 6, c = idx & 63;
            Ks[r * SP + c] = Kh[(size_t)(kst + r) * HD + c];
            Vs[r * SP + c] = Vh[(size_t)(kst + r) * HD + c];
        }
        __syncthreads();

        // Scores: 64x64 tile, 4x4 per thread
        float sc[4][4];
#pragma unroll
        for (int i = 0; i < 4; i++)
#pragma unroll
            for (int j = 0; j < 4; j++) sc[i][j] = 0.0f;

#pragma unroll 8
        for (int d = 0; d < 64; d++) {
            float a[4], b[4];
#pragma unroll
            for (int i = 0; i < 4; i++) a[i] = Qs[(ty * 4 + i) * SP + d];
#pragma unroll
            for (int j = 0; j < 4; j++) b[j] = Ks[(tx * 4 + j) * SP + d];
#pragma unroll
            for (int i = 0; i < 4; i++)
#pragma unroll
                for (int j = 0; j < 4; j++) sc[i][j] = fmaf(a[i], b[j], sc[i][j]);
        }

        // Scale + mask, per-thread row maxima
        float tmax[4];
#pragma unroll
        for (int i = 0; i < 4; i++) {
            const int iq = qbase + ty * 4 + i;
            float mx = -1e30f;
#pragma unroll
            for (int j = 0; j < 4; j++) {
                const int jk = kst + tx * 4 + j;
                const bool valid = (jk <= iq) && ((jk >= iq - WIN_HALF) || (jk < NGLOB));
                const float v = valid ? sc[i][j] * scale : -1e30f;
                sc[i][j] = v;
                mx = fmaxf(mx, v);
            }
            tmax[i] = mx;
        }

        // Reduce row max across the 16 threads of this row group (same warp half)
#pragma unroll
        for (int off = 1; off < 16; off <<= 1)
#pragma unroll
            for (int i = 0; i < 4; i++)
                tmax[i] = fmaxf(tmax[i], __shfl_xor_sync(0xffffffffu, tmax[i], off));

        // Online softmax update
        float psum[4];
#pragma unroll
        for (int i = 0; i < 4; i++) {
            const float mnew = fmaxf(m_r[i], tmax[i]);
            const float alpha = __expf(m_r[i] - mnew);
            m_r[i] = mnew;
            float ps = 0.0f;
#pragma unroll
            for (int j = 0; j < 4; j++) {
                const float p = __expf(sc[i][j] - mnew);
                sc[i][j] = p;
                ps += p;
            }
            psum[i] = ps;
            l_r[i] *= alpha;
#pragma unroll
            for (int j = 0; j < 4; j++) acc[i][j] *= alpha;
        }
#pragma unroll
        for (int off = 1; off < 16; off <<= 1)
#pragma unroll
            for (int i = 0; i < 4; i++)
                psum[i] += __shfl_xor_sync(0xffffffffu, psum[i], off);
#pragma unroll
        for (int i = 0; i < 4; i++) l_r[i] += psum[i];

        // Publish P tile to shared for the PV product
#pragma unroll
        for (int i = 0; i < 4; i++)
#pragma unroll
            for (int j = 0; j < 4; j++)
                Ss[(ty * 4 + i) * SP + tx * 4 + j] = sc[i][j];
        __syncthreads();

        // O += P @ V   (64 keys)
#pragma unroll 8
        for (int c = 0; c < 64; c++) {
            float a[4], b[4];
#pragma unroll
            for (int j = 0; j < 4; j++) b[j] = Vs[c * SP + tx * 4 + j];
#pragma unroll
            for (int i = 0; i < 4; i++) a[i] = Ss[(ty * 4 + i) * SP + c];
#pragma unroll
            for (int i = 0; i < 4; i++)
#pragma unroll
                for (int j = 0; j < 4; j++) acc[i][j] = fmaf(a[i], b[j], acc[i][j]);
        }
    }

    // Normalize + store to g_attn [S][H*D]
#pragma unroll
    for (int i = 0; i < 4; i++) {
        const int s = qbase + ty * 4 + i;
        const float inv = 1.0f / l_r[i];
#pragma unroll
        for (int j = 0; j < 4; j++) {
            g_attn[(size_t)s * DIM + h * HD + tx * 4 + j] = acc[i][j] * inv;
        }
    }
}

// ---------------------------------------------------------------------------
// Launcher
// ---------------------------------------------------------------------------

extern "C" void kernel_launch(void* const* d_in, const int* in_sizes, int n_in,
                              void* d_out, int out_size)
{
    const float* x     = (const float*)d_in[0];   // [1,4096,1024]
    const float* w_qkv = (const float*)d_in[1];   // [1024,3072]
    const float* w_out = (const float*)d_in[2];   // [1024,1024]
    float* out = (float*)d_out;                   // [1,4096,1024]

    // 1) QKV projection with scatter into [H][S][D] Q/K/V
    qkv_gemm_kernel<<<dim3(NQKV / 64, SEQ / 64), 256>>>(x, w_qkv);

    // 2) Sparse attention (flash-style online softmax)
    const int smem_bytes = 4 * 64 * SP * (int)sizeof(float);  // 66560 B
    cudaFuncSetAttribute(attn_kernel, cudaFuncAttributeMaxDynamicSharedMemorySize, smem_bytes);
    attn_kernel<<<dim3(SEQ / 64, NH), 256, smem_bytes>>>();

    // 3) Output projection
    out_gemm_kernel<<<dim3(DIM / 64, SEQ / 64), 256>>>(w_out, out);
}

// round 7
// speedup vs baseline: 1.9193x; 1.9193x over previous
#include <cuda_runtime.h>
#include <cuda_bf16.h>
#include <cstdint>
#include <math.h>

// Problem constants
#define SEQ   4096
#define NH    16
#define HD    64
#define DIM   1024
#define NQKV  3072
#define WIN_HALF 128
#define NGLOB 64

// ---------------------------------------------------------------------------
// Device-global scratch (allocation-free rule)
// ---------------------------------------------------------------------------
__device__ float g_Q[NH * SEQ * HD];               // [H][S][D] fp32
__device__ float g_K[NH * SEQ * HD];
__device__ float g_V[NH * SEQ * HD];
__device__ __nv_bfloat16 g_xh[SEQ * DIM];          // x split hi/lo [S][K]
__device__ __nv_bfloat16 g_xl[SEQ * DIM];
__device__ __nv_bfloat16 g_wqT_h[NQKV * DIM];      // w_qkv^T split [N][K]
__device__ __nv_bfloat16 g_wqT_l[NQKV * DIM];
__device__ __nv_bfloat16 g_woT_h[DIM * DIM];       // w_out^T split [N][K]
__device__ __nv_bfloat16 g_woT_l[DIM * DIM];
__device__ __nv_bfloat16 g_ah[SEQ * DIM];          // attn output split [S][H*D]
__device__ __nv_bfloat16 g_al[SEQ * DIM];

// ---------------------------------------------------------------------------
// Baseline-PTX helpers (all sm_80+ baseline; no sm_103a-gated instructions)
// ---------------------------------------------------------------------------
__device__ __forceinline__ uint32_t smem_to_u32(const void* smem_ptr) {
    uint32_t addr;
    asm("{ .reg .u64 tmp; cvta.to.shared.u64 tmp, %1; cvt.u32.u64 %0, tmp; }"
        : "=r"(addr) : "l"(smem_ptr));
    return addr;
}

__device__ __forceinline__ void cp_async16(uint32_t dst, const void* src) {
    asm volatile("cp.async.cg.shared.global [%0], [%1], 16;"
                 :: "r"(dst), "l"(src));
}
#define CP_ASYNC_COMMIT() asm volatile("cp.async.commit_group;" ::: "memory")
#define CP_ASYNC_WAIT_1() asm volatile("cp.async.wait_group 1;" ::: "memory")

__device__ __forceinline__ void ldsm_x4(uint32_t& r0, uint32_t& r1,
                                        uint32_t& r2, uint32_t& r3, uint32_t addr) {
    asm volatile("ldmatrix.sync.aligned.m8n8.x4.shared.b16 {%0,%1,%2,%3}, [%4];"
                 : "=r"(r0), "=r"(r1), "=r"(r2), "=r"(r3) : "r"(addr));
}

__device__ __forceinline__ void mma_bf16(float* c, const uint32_t* a, const uint32_t* b) {
    asm volatile(
        "mma.sync.aligned.m16n8k16.row.col.f32.bf16.bf16.f32 "
        "{%0,%1,%2,%3}, {%4,%5,%6,%7}, {%8,%9}, {%0,%1,%2,%3};"
        : "+f"(c[0]), "+f"(c[1]), "+f"(c[2]), "+f"(c[3])
        : "r"(a[0]), "r"(a[1]), "r"(a[2]), "r"(a[3]), "r"(b[0]), "r"(b[1]));
}

// ---------------------------------------------------------------------------
// bf16 split helper: v = hi + lo (each bf16), residual ~2^-16 * |v|
// ---------------------------------------------------------------------------
__device__ __forceinline__ void split_bf(float v, __nv_bfloat16& h, __nv_bfloat16& l) {
    h = __float2bfloat16(v);
    l = __float2bfloat16(v - __bfloat162float(h));
}

// ---------------------------------------------------------------------------
// Pre-pass 1: split x -> g_xh / g_xl
// ---------------------------------------------------------------------------
__global__ void conv_x_kernel(const float* __restrict__ x) {
    const int i = (blockIdx.x * blockDim.x + threadIdx.x) * 4;
    float4 v = *reinterpret_cast<const float4*>(x + i);
    __nv_bfloat16 h0, h1, h2, h3, l0, l1, l2, l3;
    split_bf(v.x, h0, l0); split_bf(v.y, h1, l1);
    split_bf(v.z, h2, l2); split_bf(v.w, h3, l3);
    g_xh[i + 0] = h0; g_xh[i + 1] = h1; g_xh[i + 2] = h2; g_xh[i + 3] = h3;
    g_xl[i + 0] = l0; g_xl[i + 1] = l1; g_xl[i + 2] = l2; g_xl[i + 3] = l3;
}

// ---------------------------------------------------------------------------
// Pre-pass 2: transpose + split W[K][N] -> [N][K] hi/lo
// ---------------------------------------------------------------------------
__global__ void tconv_wq_kernel(const float* __restrict__ W) {
    __shared__ float t[32][33];
    const int n0 = blockIdx.x * 32, k0 = blockIdx.y * 32;
    const int tx = threadIdx.x, ty = threadIdx.y;
#pragma unroll
    for (int i = 0; i < 32; i += 8)
        t[ty + i][tx] = W[(size_t)(k0 + ty + i) * NQKV + n0 + tx];
    __syncthreads();
#pragma unroll
    for (int i = 0; i < 32; i += 8) {
        float v = t[tx][ty + i];
        __nv_bfloat16 h, l; split_bf(v, h, l);
        g_wqT_h[(size_t)(n0 + ty + i) * DIM + k0 + tx] = h;
        g_wqT_l[(size_t)(n0 + ty + i) * DIM + k0 + tx] = l;
    }
}

__global__ void tconv_wo_kernel(const float* __restrict__ W) {
    __shared__ float t[32][33];
    const int n0 = blockIdx.x * 32, k0 = blockIdx.y * 32;
    const int tx = threadIdx.x, ty = threadIdx.y;
#pragma unroll
    for (int i = 0; i < 32; i += 8)
        t[ty + i][tx] = W[(size_t)(k0 + ty + i) * DIM + n0 + tx];
    __syncthreads();
#pragma unroll
    for (int i = 0; i < 32; i += 8) {
        float v = t[tx][ty + i];
        __nv_bfloat16 h, l; split_bf(v, h, l);
        g_woT_h[(size_t)(n0 + ty + i) * DIM + k0 + tx] = h;
        g_woT_l[(size_t)(n0 + ty + i) * DIM + k0 + tx] = l;
    }
}

// ---------------------------------------------------------------------------
// HMMA GEMM: C[M x N] = A[M x 1024] @ B^T (B stored [N][1024] bf16 hi/lo)
// Split-bf16 3-term, fp32 accumulate via mma.sync.m16n8k16.
// CTA tile 128x128, BK=32, 256 threads (warp grid 2M x 4N, warp tile 64x32).
// cp.async double-buffered. mode 0: scatter Q/K/V; mode 1: write Cout.
// ---------------------------------------------------------------------------
#define AP_BYTES   80        // padded row pitch (32 bf16 -> 40 elems = 80B)
#define T_TILE     10240     // one 128-row tile: 128 * 80
#define STAGE_B    40960     // 4 tiles (Ah, Al, Bh, Bl)
#define GEMM_SMEM  (2 * STAGE_B)

__global__ void __launch_bounds__(256, 1) gemm_mma_kernel(float* __restrict__ Cout, int mode)
{
    extern __shared__ char smem_raw[];
    const uint32_t sb = smem_to_u32(smem_raw);

    const int tid  = threadIdx.x;
    const int wid  = tid >> 5;
    const int lane = tid & 31;
    const int wm   = wid & 1;        // 0..1  (M)
    const int wn   = wid >> 1;       // 0..3  (N)
    const int m0   = blockIdx.y * 128;
    const int n0   = blockIdx.x * 128;

    const __nv_bfloat16 *Ah, *Al, *Bh, *Bl;
    if (mode == 0) { Ah = g_xh; Al = g_xl; Bh = g_wqT_h; Bl = g_wqT_l; }
    else           { Ah = g_ah; Al = g_al; Bh = g_woT_h; Bl = g_woT_l; }

    // Per-thread cp.async mapping (8 chunks of 16B per stage):
    // e -> tile = e>>1 (0:Ah 1:Al 2:Bh 3:Bl), cid = ((e&1)<<8)|tid,
    // r = cid>>2 (row 0..127), ch = cid&3 (16B chunk in 64B row).
    const int cid0 = tid;
    const int cid1 = 256 + tid;

    auto load_stage = [&](int stage, int kt) {
        const int k0 = kt * 32;
        const uint32_t sbase = sb + stage * STAGE_B;
#pragma unroll
        for (int e = 0; e < 8; e++) {
            const int tile = e >> 1;
            const int cid  = (e & 1) ? cid1 : cid0;
            const int r    = cid >> 2;
            const int ch   = cid & 3;
            const __nv_bfloat16* src;
            if (tile == 0)      src = Ah + (size_t)(m0 + r) * DIM + k0 + ch * 8;
            else if (tile == 1) src = Al + (size_t)(m0 + r) * DIM + k0 + ch * 8;
            else if (tile == 2) src = Bh + (size_t)(n0 + r) * DIM + k0 + ch * 8;
            else                src = Bl + (size_t)(n0 + r) * DIM + k0 + ch * 8;
            cp_async16(sbase + tile * T_TILE + r * AP_BYTES + ch * 16, src);
        }
    };

    // Fragment base addresses (byte offsets within a stage)
    const uint32_t a_off = (uint32_t)((wm * 64 + (lane & 15)) * AP_BYTES + (lane >> 4) * 16);
    const uint32_t b_off = (uint32_t)((wn * 32 + (lane & 15)) * AP_BYTES + (lane >> 4) * 16) + 2u * T_TILE;

    float acc[4][4][4];
#pragma unroll
    for (int i = 0; i < 4; i++)
#pragma unroll
        for (int j = 0; j < 4; j++)
#pragma unroll
            for (int e = 0; e < 4; e++) acc[i][j][e] = 0.0f;

    // Prologue: fill both stages
    load_stage(0, 0); CP_ASYNC_COMMIT();
    load_stage(1, 1); CP_ASYNC_COMMIT();

    for (int kt = 0; kt < 32; kt++) {
        CP_ASYNC_WAIT_1();
        __syncthreads();
        const uint32_t sbase = sb + (uint32_t)(kt & 1) * STAGE_B;

#pragma unroll
        for (int ks = 0; ks < 2; ks++) {
            uint32_t ah[4][4], al[4][4], bh[4][2], bl[4][2];
#pragma unroll
            for (int i = 0; i < 4; i++) {
                const uint32_t ad = sbase + a_off + i * (16 * AP_BYTES) + ks * 32;
                ldsm_x4(ah[i][0], ah[i][1], ah[i][2], ah[i][3], ad);
                ldsm_x4(al[i][0], al[i][1], al[i][2], al[i][3], ad + T_TILE);
            }
#pragma unroll
            for (int p = 0; p < 2; p++) {
                const uint32_t bd = sbase + b_off + p * (16 * AP_BYTES) + ks * 32;
                uint32_t t0, t1, t2, t3;
                ldsm_x4(t0, t1, t2, t3, bd);
                bh[2*p][0] = t0; bh[2*p][1] = t2; bh[2*p+1][0] = t1; bh[2*p+1][1] = t3;
                ldsm_x4(t0, t1, t2, t3, bd + T_TILE);
                bl[2*p][0] = t0; bl[2*p][1] = t2; bl[2*p+1][0] = t1; bl[2*p+1][1] = t3;
            }
#pragma unroll
            for (int i = 0; i < 4; i++)
#pragma unroll
                for (int j = 0; j < 4; j++) {
                    mma_bf16(acc[i][j], ah[i], bh[j]);
                    mma_bf16(acc[i][j], al[i], bh[j]);
                    mma_bf16(acc[i][j], ah[i], bl[j]);
                }
        }

        __syncthreads();
        if (kt + 2 < 32) load_stage(kt & 1, kt + 2);
        CP_ASYNC_COMMIT();
    }

    // Epilogue: frag (i,j): rows m_lo = wm*64 + i*16 + lane/4 (+8), cols
    // n = wn*32 + j*8 + (lane%3..)*2 pairs.
    const int mbase = m0 + wm * 64 + (lane >> 2);
    const int nbase = n0 + wn * 32 + (lane & 3) * 2;
#pragma unroll
    for (int i = 0; i < 4; i++) {
        const int mlo = mbase + i * 16;
#pragma unroll
        for (int j = 0; j < 4; j++) {
            const int n = nbase + j * 8;
            if (mode == 0) {
                const int t = n >> 10, rem = n & 1023, h = rem >> 6, d = rem & 63;
                float* base = (t == 0 ? g_Q : (t == 1 ? g_K : g_V)) + (size_t)h * SEQ * HD + d;
                float2 v0; v0.x = acc[i][j][0]; v0.y = acc[i][j][1];
                float2 v1; v1.x = acc[i][j][2]; v1.y = acc[i][j][3];
                *reinterpret_cast<float2*>(base + (size_t)mlo * HD)       = v0;
                *reinterpret_cast<float2*>(base + (size_t)(mlo + 8) * HD) = v1;
            } else {
                float2 v0; v0.x = acc[i][j][0]; v0.y = acc[i][j][1];
                float2 v1; v1.x = acc[i][j][2]; v1.y = acc[i][j][3];
                *reinterpret_cast<float2*>(Cout + (size_t)mlo * DIM + n)       = v0;
                *reinterpret_cast<float2*>(Cout + (size_t)(mlo + 8) * DIM + n) = v1;
            }
        }
    }
}

// ---------------------------------------------------------------------------
// Attention: flash-style online softmax over <=4 key tiles of 64.
// fp32 math; epilogue writes split bf16 into g_ah/g_al for the out-proj GEMM.
// ---------------------------------------------------------------------------
#define SP 65

__global__ void attn_kernel()
{
    extern __shared__ float sm[];
    float* Qs = sm;
    float* Ks = Qs + 64 * SP;
    float* Vs = Ks + 64 * SP;
    float* Ss = Vs + 64 * SP;

    const int h  = blockIdx.y;
    const int qt = blockIdx.x;
    const int qbase = qt * 64;

    const int tid = threadIdx.x;
    const int ty = tid >> 4;
    const int tx = tid & 15;

    const float* Qh = g_Q + (size_t)h * SEQ * HD;
    const float* Kh = g_K + (size_t)h * SEQ * HD;
    const float* Vh = g_V + (size_t)h * SEQ * HD;

#pragma unroll
    for (int e = 0; e < 16; e++) {
        const int idx = tid + e * 256;
        const int r = idx >> 6, c = idx & 63;
        Qs[r * SP + c] = Qh[(size_t)(qbase + r) * HD + c];
    }

    float m_r[4], l_r[4], acc[4][4];
#pragma unroll
    for (int i = 0; i < 4; i++) {
        m_r[i] = -1e30f;
        l_r[i] = 0.0f;
#pragma unroll
        for (int j = 0; j < 4; j++) acc[i][j] = 0.0f;
    }

    int starts[4];
    int ns = 0;
    starts[ns++] = 0;
    if (qbase - 128 > 0) starts[ns++] = qbase - 128;
    if (qbase - 64  > 0) starts[ns++] = qbase - 64;
    if (qbase       > 0) starts[ns++] = qbase;

    const float scale = 0.125f;

    for (int it = 0; it < ns; it++) {
        const int kst = starts[it];
        __syncthreads();
#pragma unroll
        for (int e = 0; e < 16; e++) {
            const int idx = tid + e * 256;
            const int r = idx >> 6, c = idx & 63;
            Ks[r * SP + c] = Kh[(size_t)(kst + r) * HD + c];
            Vs[r * SP + c] = Vh[(size_t)(kst + r) * HD + c];
        }
        __syncthreads();

        float sc[4][4];
#pragma unroll
        for (int i = 0; i < 4; i++)
#pragma unroll
            for (int j = 0; j < 4; j++) sc[i][j] = 0.0f;

#pragma unroll 8
        for (int d = 0; d < 64; d++) {
            float a[4], b[4];
#pragma unroll
            for (int i = 0; i < 4; i++) a[i] = Qs[(ty * 4 + i) * SP + d];
#pragma unroll
            for (int j = 0; j < 4; j++) b[j] = Ks[(tx * 4 + j) * SP + d];
#pragma unroll
            for (int i = 0; i < 4; i++)
#pragma unroll
                for (int j = 0; j < 4; j++) sc[i][j] = fmaf(a[i], b[j], sc[i][j]);
        }

        float tmax[4];
#pragma unroll
        for (int i = 0; i < 4; i++) {
            const int iq = qbase + ty * 4 + i;
            float mx = -1e30f;
#pragma unroll
            for (int j = 0; j < 4; j++) {
                const int jk = kst + tx * 4 + j;
                const bool valid = (jk <= iq) && ((jk >= iq - WIN_HALF) || (jk < NGLOB));
                const float v = valid ? sc[i][j] * scale : -1e30f;
                sc[i][j] = v;
                mx = fmaxf(mx, v);
            }
            tmax[i] = mx;
        }

#pragma unroll
        for (int off = 1; off < 16; off <<= 1)
#pragma unroll
            for (int i = 0; i < 4; i++)
                tmax[i] = fmaxf(tmax[i], __shfl_xor_sync(0xffffffffu, tmax[i], off));

        float psum[4];
#pragma unroll
        for (int i = 0; i < 4; i++) {
            const float mnew = fmaxf(m_r[i], tmax[i]);
            const float alpha = __expf(m_r[i] - mnew);
            m_r[i] = mnew;
            float ps = 0.0f;
#pragma unroll
            for (int j = 0; j < 4; j++) {
                const float p = __expf(sc[i][j] - mnew);
                sc[i][j] = p;
                ps += p;
            }
            psum[i] = ps;
            l_r[i] *= alpha;
#pragma unroll
            for (int j = 0; j < 4; j++) acc[i][j] *= alpha;
        }
#pragma unroll
        for (int off = 1; off < 16; off <<= 1)
#pragma unroll
            for (int i = 0; i < 4; i++)
                psum[i] += __shfl_xor_sync(0xffffffffu, psum[i], off);
#pragma unroll
        for (int i = 0; i < 4; i++) l_r[i] += psum[i];

#pragma unroll
        for (int i = 0; i < 4; i++)
#pragma unroll
            for (int j = 0; j < 4; j++)
                Ss[(ty * 4 + i) * SP + tx * 4 + j] = sc[i][j];
        __syncthreads();

#pragma unroll 8
        for (int c = 0; c < 64; c++) {
            float a[4], b[4];
#pragma unroll
            for (int j = 0; j < 4; j++) b[j] = Vs[c * SP + tx * 4 + j];
#pragma unroll
            for (int i = 0; i < 4; i++) a[i] = Ss[(ty * 4 + i) * SP + c];
#pragma unroll
            for (int i = 0; i < 4; i++)
#pragma unroll
                for (int j = 0; j < 4; j++) acc[i][j] = fmaf(a[i], b[j], acc[i][j]);
        }
    }

    // Normalize + split-store to g_ah/g_al [S][H*D]
#pragma unroll
    for (int i = 0; i < 4; i++) {
        const int s = qbase + ty * 4 + i;
        const float inv = 1.0f / l_r[i];
#pragma unroll
        for (int j = 0; j < 4; j++) {
            const float o = acc[i][j] * inv;
            __nv_bfloat16 hh, ll; split_bf(o, hh, ll);
            const size_t oi = (size_t)s * DIM + h * HD + tx * 4 + j;
            g_ah[oi] = hh;
            g_al[oi] = ll;
        }
    }
}

// ---------------------------------------------------------------------------
// Launcher
// ---------------------------------------------------------------------------
extern "C" void kernel_launch(void* const* d_in, const int* in_sizes, int n_in,
                              void* d_out, int out_size)
{
    const float* x     = (const float*)d_in[0];   // [1,4096,1024]
    const float* w_qkv = (const float*)d_in[1];   // [1024,3072]
    const float* w_out = (const float*)d_in[2];   // [1024,1024]
    float* out = (float*)d_out;                   // [1,4096,1024]

    // Pre-pass: split/transpose inputs to bf16 hi/lo
    conv_x_kernel<<<SEQ * DIM / 4 / 256, 256>>>(x);
    tconv_wq_kernel<<<dim3(NQKV / 32, DIM / 32), dim3(32, 8)>>>(w_qkv);
    tconv_wo_kernel<<<dim3(DIM / 32, DIM / 32), dim3(32, 8)>>>(w_out);

    // 1) QKV projection (HMMA, scatter into g_Q/g_K/g_V)
    cudaFuncSetAttribute(gemm_mma_kernel, cudaFuncAttributeMaxDynamicSharedMemorySize, GEMM_SMEM);
    gemm_mma_kernel<<<dim3(NQKV / 128, SEQ / 128), 256, GEMM_SMEM>>>(nullptr, 0);

    // 2) Sparse attention (fp32, writes split-bf16 attn output)
    const int attn_smem = 4 * 64 * SP * (int)sizeof(float);
    cudaFuncSetAttribute(attn_kernel, cudaFuncAttributeMaxDynamicSharedMemorySize, attn_smem);
    attn_kernel<<<dim3(SEQ / 64, NH), 256, attn_smem>>>();

    // 3) Output projection (HMMA)
    gemm_mma_kernel<<<dim3(DIM / 128, SEQ / 128), 256, GEMM_SMEM>>>(out, 1);
}